// round 1
// baseline (speedup 1.0000x reference)
#include <cuda_runtime.h>
#include <cuda_bf16.h>
#include <math.h>
#include <stdint.h>

// Problem dims
constexpr int NB  = 2;
constexpr int NS  = 1024;
constexpr int ND  = 512;
constexpr int NH  = 8;
constexpr int NDH = 64;
constexpr int NL  = 6;
constexpr int NV  = 50257;
constexpr int NBS = NB * NS;      // 2048
constexpr int NFF = 4 * ND;       // 2048
constexpr float INV_SCALE = 0.04419417382415922f; // 1/sqrt(512)

// ---------------- scratch (static device globals; no allocation) -------------
__device__ float g_x[NBS * ND];
__device__ float g_h[NBS * ND];
__device__ float g_q[NBS * ND];
__device__ float g_k[NBS * ND];
__device__ float g_v[NBS * ND];
__device__ float g_o[NBS * ND];
__device__ float g_ff[NBS * NFF];
__device__ float g_att[(size_t)NB * NH * NS * NS];   // 64 MB
__device__ float g_nll[NBS];

// ---------------- embedding --------------------------------------------------
__global__ void embed_k(const int* __restrict__ idx, const int* __restrict__ mask,
                        const float* __restrict__ tok, const float* __restrict__ pos,
                        float* __restrict__ x) {
    int row = blockIdx.x;               // b*NS + s
    int b = row / NS, s = row % NS;
    int t = idx[b * (NS + 1) + s];
    float m = (float)mask[row];
    const float* tr = tok + (size_t)t * ND;
    const float* pr = pos + (size_t)s * ND;
    float* xr = x + (size_t)row * ND;
    for (int d = threadIdx.x; d < ND; d += blockDim.x)
        xr[d] = (tr[d] + pr[d]) * m;
}

// ---------------- layernorm (row = blockIdx.x, 256 thr, 2 elems/thr) ---------
__global__ __launch_bounds__(256) void ln_k(const float* __restrict__ x,
                                            const float* __restrict__ g,
                                            const float* __restrict__ be,
                                            float* __restrict__ out) {
    int row = blockIdx.x;
    int tid = threadIdx.x;
    const float* xr = x + (size_t)row * ND;
    float v0 = xr[tid], v1 = xr[tid + 256];
    __shared__ float red[256];
    red[tid] = v0 + v1;
    __syncthreads();
    for (int o = 128; o > 0; o >>= 1) { if (tid < o) red[tid] += red[tid + o]; __syncthreads(); }
    float mean = red[0] * (1.0f / ND);
    __syncthreads();
    float d0 = v0 - mean, d1 = v1 - mean;
    red[tid] = d0 * d0 + d1 * d1;
    __syncthreads();
    for (int o = 128; o > 0; o >>= 1) { if (tid < o) red[tid] += red[tid + o]; __syncthreads(); }
    float inv = rsqrtf(red[0] * (1.0f / ND) + 1e-5f);
    float* orow = out + (size_t)row * ND;
    orow[tid]       = d0 * inv * g[tid]       + be[tid];
    orow[tid + 256] = d1 * inv * g[tid + 256] + be[tid + 256];
}

// ---------------- GEMM: C[M,N] = act(A[M,K] @ B[K,N] + bias) + Res -----------
// BM=BN=128, BK=8, 256 threads, 8x8 micro-tile. M must be multiple of 128,
// K multiple of 8 (true for all uses). N guarded.
template <int ACT, bool HAS_BIAS, bool HAS_RES>
__global__ __launch_bounds__(256) void gemm_k(const float* __restrict__ A,
                                              const float* __restrict__ Bm,
                                              const float* __restrict__ bias,
                                              const float* __restrict__ Res,
                                              float* __restrict__ C,
                                              int M, int N, int K) {
    constexpr int BM = 128, BN = 128, BK = 8;
    __shared__ float As[BK][BM + 4];
    __shared__ float Bs[BK][BN + 4];
    int tid = threadIdx.x;
    int m0 = blockIdx.y * BM, n0 = blockIdx.x * BN;
    int trow = tid >> 4, tcol = tid & 15;
    float acc[8][8];
#pragma unroll
    for (int i = 0; i < 8; i++)
#pragma unroll
        for (int j = 0; j < 8; j++) acc[i][j] = 0.f;

    int ar = tid >> 1, ac = (tid & 1) * 4;   // A tile: one float4 per thread
    for (int k0 = 0; k0 < K; k0 += BK) {
        float4 a4 = *reinterpret_cast<const float4*>(A + (size_t)(m0 + ar) * K + k0 + ac);
        As[ac + 0][ar] = a4.x; As[ac + 1][ar] = a4.y;
        As[ac + 2][ar] = a4.z; As[ac + 3][ar] = a4.w;
#pragma unroll
        for (int i = 0; i < 4; i++) {
            int idx = tid + i * 256;
            int r = idx >> 7, c = idx & 127;
            int col = n0 + c;
            Bs[r][c] = (col < N) ? Bm[(size_t)(k0 + r) * N + col] : 0.f;
        }
        __syncthreads();
#pragma unroll
        for (int kk = 0; kk < BK; kk++) {
            float ra[8], rb[8];
            *(float4*)&ra[0] = *(float4*)&As[kk][trow * 8];
            *(float4*)&ra[4] = *(float4*)&As[kk][trow * 8 + 4];
            *(float4*)&rb[0] = *(float4*)&Bs[kk][tcol * 8];
            *(float4*)&rb[4] = *(float4*)&Bs[kk][tcol * 8 + 4];
#pragma unroll
            for (int i = 0; i < 8; i++)
#pragma unroll
                for (int j = 0; j < 8; j++) acc[i][j] += ra[i] * rb[j];
        }
        __syncthreads();
    }
#pragma unroll
    for (int i = 0; i < 8; i++) {
        int row = m0 + trow * 8 + i;
#pragma unroll
        for (int j = 0; j < 8; j++) {
            int col = n0 + tcol * 8 + j;
            if (col < N) {
                float v = acc[i][j];
                if (HAS_BIAS) v += bias[col];
                if (ACT == 1) v = 0.5f * v * (1.0f + erff(v * 0.70710678118654752f));
                if (HAS_RES) v += Res[(size_t)row * N + col];
                C[(size_t)row * N + col] = v;
            }
        }
    }
}

// ---------------- attention: scores = Q @ K^T / sqrt(D), causal --------------
// grid (NS/32 [k], NS/32 [q], NB*NH), 256 threads. Skips fully-masked tiles.
__global__ __launch_bounds__(256) void qk_k(const float* __restrict__ Q,
                                            const float* __restrict__ Kt,
                                            float* __restrict__ Att) {
    int k0 = blockIdx.x * 32, q0 = blockIdx.y * 32;
    if (k0 > q0 + 31) return;
    int bh = blockIdx.z;
    int b = bh / NH, h = bh % NH;
    const float* qbase = Q + (size_t)b * NS * ND + h * NDH;
    const float* kbase = Kt + (size_t)b * NS * ND + h * NDH;
    __shared__ float Qs[32][NDH + 4];
    __shared__ float Ks[32][NDH + 4];
    int tid = threadIdx.x;
#pragma unroll
    for (int i = 0; i < 2; i++) {
        int idx = tid + i * 256;
        int r = idx >> 4, c4 = (idx & 15) * 4;
        *(float4*)&Qs[r][c4] = *(const float4*)&qbase[(size_t)(q0 + r) * ND + c4];
        *(float4*)&Ks[r][c4] = *(const float4*)&kbase[(size_t)(k0 + r) * ND + c4];
    }
    __syncthreads();
    int tx = tid & 31;         // local k
    int ty = tid >> 5;         // q group (0..7), 4 rows each
    float acc[4] = {0.f, 0.f, 0.f, 0.f};
#pragma unroll
    for (int d4 = 0; d4 < NDH / 4; d4++) {
        float4 kv = *(float4*)&Ks[tx][d4 * 4];
#pragma unroll
        for (int i = 0; i < 4; i++) {
            float4 qv = *(float4*)&Qs[ty * 4 + i][d4 * 4];
            acc[i] += qv.x * kv.x + qv.y * kv.y + qv.z * kv.z + qv.w * kv.w;
        }
    }
    int k = k0 + tx;
#pragma unroll
    for (int i = 0; i < 4; i++) {
        int q = q0 + ty * 4 + i;
        float v = (k <= q) ? acc[i] * INV_SCALE : -INFINITY;
        Att[((size_t)bh * NS + q) * NS + k] = v;
    }
}

// ---------------- softmax per row; zeros above diagonal ----------------------
__global__ __launch_bounds__(256) void softmax_k(float* __restrict__ Att) {
    int row = blockIdx.x;              // bh*NS + q
    int q = row % NS;
    float* a = Att + (size_t)row * NS;
    int n = q + 1;
    int tid = threadIdx.x;
    __shared__ float red[256];
    float mx = -3.4e38f;
    for (int i = tid; i < n; i += 256) mx = fmaxf(mx, a[i]);
    red[tid] = mx; __syncthreads();
    for (int o = 128; o > 0; o >>= 1) { if (tid < o) red[tid] = fmaxf(red[tid], red[tid + o]); __syncthreads(); }
    mx = red[0]; __syncthreads();
    float sum = 0.f;
    for (int i = tid; i < n; i += 256) sum += __expf(a[i] - mx);
    red[tid] = sum; __syncthreads();
    for (int o = 128; o > 0; o >>= 1) { if (tid < o) red[tid] += red[tid + o]; __syncthreads(); }
    float inv = 1.0f / red[0];
    for (int i = tid; i < n; i += 256) a[i] = __expf(a[i] - mx) * inv;
    for (int i = n + tid; i < NS; i += 256) a[i] = 0.f;
}

// ---------------- out = Att @ V, causal chunk skip ---------------------------
// grid (NS/32 [q], NB*NH), 256 threads; block = 32 q-rows x 64 d-cols.
__global__ __launch_bounds__(256) void av_k(const float* __restrict__ Att,
                                            const float* __restrict__ Vv,
                                            float* __restrict__ O) {
    int q0 = blockIdx.x * 32;
    int bh = blockIdx.y;
    int b = bh / NH, h = bh % NH;
    const float* abase = Att + (size_t)bh * NS * NS;
    const float* vbase = Vv + (size_t)b * NS * ND + h * NDH;
    __shared__ float Asm[32][33];
    __shared__ float Vs[32][NDH + 4];
    int tid = threadIdx.x;
    int tx = tid & 15, ty = tid >> 4;
    float acc[2][4] = {};
    for (int kc = 0; kc <= q0; kc += 32) {
#pragma unroll
        for (int i = 0; i < 4; i++) {
            int idx = tid + i * 256;
            int r = idx >> 5, c = idx & 31;
            Asm[r][c] = abase[(size_t)(q0 + r) * NS + kc + c];
        }
#pragma unroll
        for (int i = 0; i < 2; i++) {
            int idx = tid + i * 256;
            int r = idx >> 4, c4 = (idx & 15) * 4;
            *(float4*)&Vs[r][c4] = *(const float4*)&vbase[(size_t)(kc + r) * ND + c4];
        }
        __syncthreads();
#pragma unroll
        for (int k = 0; k < 32; k++) {
            float4 v4 = *(float4*)&Vs[k][tx * 4];
            float a0 = Asm[ty * 2][k];
            float a1 = Asm[ty * 2 + 1][k];
            acc[0][0] += a0 * v4.x; acc[0][1] += a0 * v4.y;
            acc[0][2] += a0 * v4.z; acc[0][3] += a0 * v4.w;
            acc[1][0] += a1 * v4.x; acc[1][1] += a1 * v4.y;
            acc[1][2] += a1 * v4.z; acc[1][3] += a1 * v4.w;
        }
        __syncthreads();
    }
#pragma unroll
    for (int i = 0; i < 2; i++) {
        int q = q0 + ty * 2 + i;
        float4 r4 = make_float4(acc[i][0], acc[i][1], acc[i][2], acc[i][3]);
        *(float4*)&O[((size_t)b * NS + q) * ND + h * NDH + tx * 4] = r4;
    }
}

// ---------------- loss: per-row logsumexp + target gather --------------------
__global__ __launch_bounds__(512) void loss_row_k(const float* __restrict__ logits,
                                                  const int* __restrict__ idx,
                                                  const int* __restrict__ mask,
                                                  float* __restrict__ nll) {
    int row = blockIdx.x;
    int b = row / NS, s = row % NS;
    const float* lr = logits + (size_t)row * NV;
    int tid = threadIdx.x;
    __shared__ float red[512];
    float mx = -3.4e38f;
    for (int i = tid; i < NV; i += 512) mx = fmaxf(mx, lr[i]);
    red[tid] = mx; __syncthreads();
    for (int o = 256; o > 0; o >>= 1) { if (tid < o) red[tid] = fmaxf(red[tid], red[tid + o]); __syncthreads(); }
    mx = red[0]; __syncthreads();
    float sum = 0.f;
    for (int i = tid; i < NV; i += 512) sum += __expf(lr[i] - mx);
    red[tid] = sum; __syncthreads();
    for (int o = 256; o > 0; o >>= 1) { if (tid < o) red[tid] += red[tid + o]; __syncthreads(); }
    if (tid == 0) {
        int tgt = idx[b * (NS + 1) + s + 1];
        float lse = mx + logf(red[0]);
        nll[row] = (lse - lr[tgt]) * (float)mask[row];
    }
}

__global__ __launch_bounds__(1024) void loss_final_k(const float* __restrict__ nll,
                                                     float* __restrict__ out) {
    __shared__ float red[1024];
    int tid = threadIdx.x;
    red[tid] = nll[tid] + nll[tid + 1024];
    __syncthreads();
    for (int o = 512; o > 0; o >>= 1) { if (tid < o) red[tid] += red[tid + o]; __syncthreads(); }
    if (tid == 0) out[0] = red[0] * (1.0f / (float)NBS);
}

// ---------------- host orchestration -----------------------------------------
extern "C" void kernel_launch(void* const* d_in, const int* in_sizes, int n_in,
                              void* d_out, int out_size) {
    const int*   idx  = (const int*)d_in[0];
    const int*   mask = (const int*)d_in[1];
    const float* tok  = (const float*)d_in[2];
    const float* pos  = (const float*)d_in[3];
    const float* Wq   = (const float*)d_in[4];
    const float* bq   = (const float*)d_in[5];
    const float* Wk   = (const float*)d_in[6];
    const float* bk   = (const float*)d_in[7];
    const float* Wv   = (const float*)d_in[8];
    const float* bv   = (const float*)d_in[9];
    const float* Wo   = (const float*)d_in[10];
    const float* bo   = (const float*)d_in[11];
    const float* ln1g = (const float*)d_in[12];
    const float* ln1b = (const float*)d_in[13];
    const float* W1   = (const float*)d_in[14];
    const float* b1   = (const float*)d_in[15];
    const float* W2   = (const float*)d_in[16];
    const float* b2   = (const float*)d_in[17];
    const float* ln2g = (const float*)d_in[18];
    const float* ln2b = (const float*)d_in[19];
    const float* lnfg = (const float*)d_in[20];
    const float* lnfb = (const float*)d_in[21];
    const float* headw= (const float*)d_in[22];
    float* out = (float*)d_out;

    float *x, *h, *q, *k, *v, *o, *ff, *att, *nll;
    cudaGetSymbolAddress((void**)&x,   g_x);
    cudaGetSymbolAddress((void**)&h,   g_h);
    cudaGetSymbolAddress((void**)&q,   g_q);
    cudaGetSymbolAddress((void**)&k,   g_k);
    cudaGetSymbolAddress((void**)&v,   g_v);
    cudaGetSymbolAddress((void**)&o,   g_o);
    cudaGetSymbolAddress((void**)&ff,  g_ff);
    cudaGetSymbolAddress((void**)&att, g_att);
    cudaGetSymbolAddress((void**)&nll, g_nll);

    embed_k<<<NBS, 256>>>(idx, mask, tok, pos, x);

    dim3 gDD(ND / 128, NBS / 128);
    dim3 gDF(NFF / 128, NBS / 128);
    dim3 gqk(NS / 32, NS / 32, NB * NH);
    dim3 gav(NS / 32, NB * NH);

    for (int l = 0; l < NL; l++) {
        const float* wq = Wq + (size_t)l * ND * ND;
        const float* wk = Wk + (size_t)l * ND * ND;
        const float* wv = Wv + (size_t)l * ND * ND;
        const float* wo = Wo + (size_t)l * ND * ND;
        const float* w1 = W1 + (size_t)l * ND * NFF;
        const float* w2 = W2 + (size_t)l * NFF * ND;

        ln_k<<<NBS, 256>>>(x, ln1g + l * ND, ln1b + l * ND, h);
        gemm_k<0, true, false><<<gDD, 256>>>(h, wq, bq + l * ND, nullptr, q, NBS, ND, ND);
        gemm_k<0, true, false><<<gDD, 256>>>(h, wk, bk + l * ND, nullptr, k, NBS, ND, ND);
        gemm_k<0, true, false><<<gDD, 256>>>(h, wv, bv + l * ND, nullptr, v, NBS, ND, ND);
        qk_k<<<gqk, 256>>>(q, k, att);
        softmax_k<<<NB * NH * NS, 256>>>(att);
        av_k<<<gav, 256>>>(att, v, o);
        gemm_k<0, true, true><<<gDD, 256>>>(o, wo, bo + l * ND, x, x, NBS, ND, ND);
        ln_k<<<NBS, 256>>>(x, ln2g + l * ND, ln2b + l * ND, h);
        gemm_k<1, true, false><<<gDF, 256>>>(h, w1, b1 + l * NFF, nullptr, ff, NBS, NFF, ND);
        gemm_k<0, true, true><<<gDD, 256>>>(ff, w2, b2 + l * ND, x, x, NBS, ND, NFF);
    }

    ln_k<<<NBS, 256>>>(x, lnfg, lnfb, h);
    dim3 gHead((NV + 127) / 128, NBS / 128);
    gemm_k<0, false, false><<<gHead, 256>>>(h, headw, nullptr, nullptr, out, NBS, NV, ND);

    loss_row_k<<<NBS, 512>>>(out, idx, mask, nll);
    loss_final_k<<<1, 1024>>>(nll, out + (size_t)NBS * NV);
}

// round 4
// speedup vs baseline: 3.2246x; 3.2246x over previous
#include <cuda_runtime.h>
#include <cuda_bf16.h>
#include <math.h>
#include <stdint.h>

// Problem dims
constexpr int NB  = 2;
constexpr int NS  = 1024;
constexpr int ND  = 512;
constexpr int NH  = 8;
constexpr int NDH = 64;
constexpr int NL  = 6;
constexpr int NV  = 50257;
constexpr int NBS = NB * NS;      // 2048
constexpr int NFF = 4 * ND;       // 2048
constexpr float INV_SCALE = 0.04419417382415922f; // 1/sqrt(512)

// ---------------- scratch (static device globals; no allocation) -------------
__device__ float g_x[NBS * ND];
__device__ float g_h[NBS * ND];
__device__ float g_q[NBS * ND];
__device__ float g_k[NBS * ND];
__device__ float g_v[NBS * ND];
__device__ float g_o[NBS * ND];
__device__ float g_ff[NBS * NFF];
__device__ float g_att[(size_t)NB * NH * NS * NS];   // 64 MB
__device__ float g_nll[NBS];

__device__ __forceinline__ float to_tf32(float x) {
    uint32_t u;
    asm("cvt.rna.tf32.f32 %0, %1;" : "=r"(u) : "f"(x));
    return __uint_as_float(u);
}

// ---------------- embedding --------------------------------------------------
__global__ void embed_k(const int* __restrict__ idx, const int* __restrict__ mask,
                        const float* __restrict__ tok, const float* __restrict__ pos,
                        float* __restrict__ x) {
    int row = blockIdx.x;               // b*NS + s
    int b = row / NS, s = row % NS;
    int t = idx[b * (NS + 1) + s];
    float m = (float)mask[row];
    const float* tr = tok + (size_t)t * ND;
    const float* pr = pos + (size_t)s * ND;
    float* xr = x + (size_t)row * ND;
    for (int d = threadIdx.x; d < ND; d += blockDim.x)
        xr[d] = (tr[d] + pr[d]) * m;
}

// ---------------- layernorm --------------------------------------------------
__global__ __launch_bounds__(256) void ln_k(const float* __restrict__ x,
                                            const float* __restrict__ g,
                                            const float* __restrict__ be,
                                            float* __restrict__ out) {
    int row = blockIdx.x;
    int tid = threadIdx.x;
    const float* xr = x + (size_t)row * ND;
    float v0 = xr[tid], v1 = xr[tid + 256];
    __shared__ float red[256];
    red[tid] = v0 + v1;
    __syncthreads();
    for (int o = 128; o > 0; o >>= 1) { if (tid < o) red[tid] += red[tid + o]; __syncthreads(); }
    float mean = red[0] * (1.0f / ND);
    __syncthreads();
    float d0 = v0 - mean, d1 = v1 - mean;
    red[tid] = d0 * d0 + d1 * d1;
    __syncthreads();
    for (int o = 128; o > 0; o >>= 1) { if (tid < o) red[tid] += red[tid + o]; __syncthreads(); }
    float inv = rsqrtf(red[0] * (1.0f / ND) + 1e-5f);
    float* orow = out + (size_t)row * ND;
    orow[tid]       = d0 * inv * g[tid]       + be[tid];
    orow[tid + 256] = d1 * inv * g[tid + 256] + be[tid + 256];
}

// ---------------- TF32 tensor-core GEMM --------------------------------------
// C[M,N] = act(A[M,K] @ B[K,N] + bias) + Res
// BM=128, BK=16, 256 threads (8 warps). BN template: 64 -> 4x2 warp grid
// (warp tile 32x32), 128 -> 2x4 warp grid (warp tile 64x32).
// BALIGN: B rows are 16B-aligned (N % 4 == 0) -> float4 loads; else scalar
// (needed for head GEMM, N=50257 odd).
// mma.sync m16n8k8 tf32. M mult of 128, K mult of 16 required; N guarded.
template <int ACT, bool HAS_BIAS, bool HAS_RES, int BN, bool BALIGN>
__global__ __launch_bounds__(256) void gemm_tc(const float* __restrict__ A,
                                               const float* __restrict__ Bm,
                                               const float* __restrict__ bias,
                                               const float* __restrict__ Res,
                                               float* __restrict__ C,
                                               int M, int N, int K) {
    constexpr int BM = 128, BK = 16;
    constexpr int WARPS_N = (BN == 128) ? 4 : 2;
    constexpr int WARPS_M = 8 / WARPS_N;
    constexpr int WM = BM / WARPS_M;          // 64 or 32
    constexpr int WN = BN / WARPS_N;          // 32
    constexpr int MT = WM / 16;               // 4 or 2
    constexpr int NT = WN / 8;                // 4

    __shared__ float As[BK][BM + 4];
    __shared__ float Bs[BK][BN + 4];

    int tid = threadIdx.x;
    int warp = tid >> 5;
    int lane = tid & 31;
    int g  = lane >> 2;       // group id 0..7
    int tg = lane & 3;        // thread in group 0..3
    int warpM = warp % WARPS_M;
    int warpN = warp / WARPS_M;

    int m0 = blockIdx.y * BM;
    int n0 = blockIdx.x * BN;

    float acc[MT][NT][4];
#pragma unroll
    for (int i = 0; i < MT; i++)
#pragma unroll
        for (int j = 0; j < NT; j++)
#pragma unroll
            for (int c = 0; c < 4; c++) acc[i][j][c] = 0.f;

    int arow = tid >> 1, ak = (tid & 1) * 8;

    for (int k0 = 0; k0 < K; k0 += BK) {
        // --- A tile: 128x16, transposed to [k][m], tf32-rounded ---
        {
            const float* ap = A + (size_t)(m0 + arow) * K + k0 + ak;
            float4 a0 = *(const float4*)ap;
            float4 a1 = *(const float4*)(ap + 4);
            As[ak + 0][arow] = to_tf32(a0.x); As[ak + 1][arow] = to_tf32(a0.y);
            As[ak + 2][arow] = to_tf32(a0.z); As[ak + 3][arow] = to_tf32(a0.w);
            As[ak + 4][arow] = to_tf32(a1.x); As[ak + 5][arow] = to_tf32(a1.y);
            As[ak + 6][arow] = to_tf32(a1.z); As[ak + 7][arow] = to_tf32(a1.w);
        }
        // --- B tile: 16xBN, tf32-rounded ---
        if (BN == 128) {
            int br = tid >> 5, bc = (tid & 31) * 4;
            if (BALIGN) {
#pragma unroll
                for (int h = 0; h < 2; h++) {
                    int r = br + h * 8;
                    float4 b4 = *(const float4*)(Bm + (size_t)(k0 + r) * N + n0 + bc);
                    Bs[r][bc + 0] = to_tf32(b4.x); Bs[r][bc + 1] = to_tf32(b4.y);
                    Bs[r][bc + 2] = to_tf32(b4.z); Bs[r][bc + 3] = to_tf32(b4.w);
                }
            } else {
#pragma unroll
                for (int h = 0; h < 2; h++) {
                    int r = br + h * 8;
                    const float* bp = Bm + (size_t)(k0 + r) * N;
#pragma unroll
                    for (int j = 0; j < 4; j++) {
                        int col = n0 + bc + j;
                        float v = (col < N) ? bp[col] : 0.f;
                        Bs[r][bc + j] = to_tf32(v);
                    }
                }
            }
        } else { // BN == 64 (always aligned uses)
            int br = tid >> 4, bc = (tid & 15) * 4;
            float4 b4 = *(const float4*)(Bm + (size_t)(k0 + br) * N + n0 + bc);
            Bs[br][bc + 0] = to_tf32(b4.x); Bs[br][bc + 1] = to_tf32(b4.y);
            Bs[br][bc + 2] = to_tf32(b4.z); Bs[br][bc + 3] = to_tf32(b4.w);
        }
        __syncthreads();

#pragma unroll
        for (int kk = 0; kk < BK; kk += 8) {
            uint32_t afr[MT][4], bfr[NT][2];
#pragma unroll
            for (int mt = 0; mt < MT; mt++) {
                int r = warpM * WM + mt * 16 + g;
                afr[mt][0] = __float_as_uint(As[kk + tg][r]);
                afr[mt][1] = __float_as_uint(As[kk + tg][r + 8]);
                afr[mt][2] = __float_as_uint(As[kk + tg + 4][r]);
                afr[mt][3] = __float_as_uint(As[kk + tg + 4][r + 8]);
            }
#pragma unroll
            for (int nt = 0; nt < NT; nt++) {
                int cc = warpN * WN + nt * 8 + g;
                bfr[nt][0] = __float_as_uint(Bs[kk + tg][cc]);
                bfr[nt][1] = __float_as_uint(Bs[kk + tg + 4][cc]);
            }
#pragma unroll
            for (int mt = 0; mt < MT; mt++)
#pragma unroll
                for (int nt = 0; nt < NT; nt++) {
                    asm volatile(
                        "mma.sync.aligned.m16n8k8.row.col.f32.tf32.tf32.f32 "
                        "{%0,%1,%2,%3}, {%4,%5,%6,%7}, {%8,%9}, {%0,%1,%2,%3};"
                        : "+f"(acc[mt][nt][0]), "+f"(acc[mt][nt][1]),
                          "+f"(acc[mt][nt][2]), "+f"(acc[mt][nt][3])
                        : "r"(afr[mt][0]), "r"(afr[mt][1]),
                          "r"(afr[mt][2]), "r"(afr[mt][3]),
                          "r"(bfr[nt][0]), "r"(bfr[nt][1]));
                }
        }
        __syncthreads();
    }

    // --- epilogue ---
#pragma unroll
    for (int mt = 0; mt < MT; mt++) {
#pragma unroll
        for (int nt = 0; nt < NT; nt++) {
            int row0 = m0 + warpM * WM + mt * 16 + g;
            int col0 = n0 + warpN * WN + nt * 8 + 2 * tg;
#pragma unroll
            for (int h = 0; h < 2; h++) {        // row, row+8
                int row = row0 + h * 8;
#pragma unroll
                for (int j = 0; j < 2; j++) {    // col, col+1
                    int col = col0 + j;
                    if (col < N) {
                        float v = acc[mt][nt][h * 2 + j];
                        if (HAS_BIAS) v += bias[col];
                        if (ACT == 1) v = 0.5f * v * (1.0f + erff(v * 0.70710678118654752f));
                        if (HAS_RES) v += Res[(size_t)row * N + col];
                        C[(size_t)row * N + col] = v;
                    }
                }
            }
        }
    }
}

// ---------------- attention: scores = Q @ K^T / sqrt(D), causal --------------
__global__ __launch_bounds__(256) void qk_k(const float* __restrict__ Q,
                                            const float* __restrict__ Kt,
                                            float* __restrict__ Att) {
    int k0 = blockIdx.x * 32, q0 = blockIdx.y * 32;
    if (k0 > q0 + 31) return;
    int bh = blockIdx.z;
    int b = bh / NH, h = bh % NH;
    const float* qbase = Q + (size_t)b * NS * ND + h * NDH;
    const float* kbase = Kt + (size_t)b * NS * ND + h * NDH;
    __shared__ float Qs[32][NDH + 4];
    __shared__ float Ks[32][NDH + 4];
    int tid = threadIdx.x;
#pragma unroll
    for (int i = 0; i < 2; i++) {
        int idx = tid + i * 256;
        int r = idx >> 4, c4 = (idx & 15) * 4;
        *(float4*)&Qs[r][c4] = *(const float4*)&qbase[(size_t)(q0 + r) * ND + c4];
        *(float4*)&Ks[r][c4] = *(const float4*)&kbase[(size_t)(k0 + r) * ND + c4];
    }
    __syncthreads();
    int tx = tid & 31;
    int ty = tid >> 5;
    float acc[4] = {0.f, 0.f, 0.f, 0.f};
#pragma unroll
    for (int d4 = 0; d4 < NDH / 4; d4++) {
        float4 kv = *(float4*)&Ks[tx][d4 * 4];
#pragma unroll
        for (int i = 0; i < 4; i++) {
            float4 qv = *(float4*)&Qs[ty * 4 + i][d4 * 4];
            acc[i] += qv.x * kv.x + qv.y * kv.y + qv.z * kv.z + qv.w * kv.w;
        }
    }
    int k = k0 + tx;
#pragma unroll
    for (int i = 0; i < 4; i++) {
        int q = q0 + ty * 4 + i;
        float v = (k <= q) ? acc[i] * INV_SCALE : -INFINITY;
        Att[((size_t)bh * NS + q) * NS + k] = v;
    }
}

// ---------------- softmax per row; zeros above diagonal ----------------------
__global__ __launch_bounds__(256) void softmax_k(float* __restrict__ Att) {
    int row = blockIdx.x;
    int q = row % NS;
    float* a = Att + (size_t)row * NS;
    int n = q + 1;
    int tid = threadIdx.x;
    __shared__ float red[256];
    float mx = -3.4e38f;
    for (int i = tid; i < n; i += 256) mx = fmaxf(mx, a[i]);
    red[tid] = mx; __syncthreads();
    for (int o = 128; o > 0; o >>= 1) { if (tid < o) red[tid] = fmaxf(red[tid], red[tid + o]); __syncthreads(); }
    mx = red[0]; __syncthreads();
    float sum = 0.f;
    for (int i = tid; i < n; i += 256) sum += __expf(a[i] - mx);
    red[tid] = sum; __syncthreads();
    for (int o = 128; o > 0; o >>= 1) { if (tid < o) red[tid] += red[tid + o]; __syncthreads(); }
    float inv = 1.0f / red[0];
    for (int i = tid; i < n; i += 256) a[i] = __expf(a[i] - mx) * inv;
    for (int i = n + tid; i < NS; i += 256) a[i] = 0.f;
}

// ---------------- out = Att @ V, causal chunk skip ---------------------------
__global__ __launch_bounds__(256) void av_k(const float* __restrict__ Att,
                                            const float* __restrict__ Vv,
                                            float* __restrict__ O) {
    int q0 = blockIdx.x * 32;
    int bh = blockIdx.y;
    int b = bh / NH, h = bh % NH;
    const float* abase = Att + (size_t)bh * NS * NS;
    const float* vbase = Vv + (size_t)b * NS * ND + h * NDH;
    __shared__ float Asm[32][33];
    __shared__ float Vs[32][NDH + 4];
    int tid = threadIdx.x;
    int tx = tid & 15, ty = tid >> 4;
    float acc[2][4] = {};
    for (int kc = 0; kc <= q0; kc += 32) {
#pragma unroll
        for (int i = 0; i < 4; i++) {
            int idx = tid + i * 256;
            int r = idx >> 5, c = idx & 31;
            Asm[r][c] = abase[(size_t)(q0 + r) * NS + kc + c];
        }
#pragma unroll
        for (int i = 0; i < 2; i++) {
            int idx = tid + i * 256;
            int r = idx >> 4, c4 = (idx & 15) * 4;
            *(float4*)&Vs[r][c4] = *(const float4*)&vbase[(size_t)(kc + r) * ND + c4];
        }
        __syncthreads();
#pragma unroll
        for (int k = 0; k < 32; k++) {
            float4 v4 = *(float4*)&Vs[k][tx * 4];
            float a0 = Asm[ty * 2][k];
            float a1 = Asm[ty * 2 + 1][k];
            acc[0][0] += a0 * v4.x; acc[0][1] += a0 * v4.y;
            acc[0][2] += a0 * v4.z; acc[0][3] += a0 * v4.w;
            acc[1][0] += a1 * v4.x; acc[1][1] += a1 * v4.y;
            acc[1][2] += a1 * v4.z; acc[1][3] += a1 * v4.w;
        }
        __syncthreads();
    }
#pragma unroll
    for (int i = 0; i < 2; i++) {
        int q = q0 + ty * 2 + i;
        float4 r4 = make_float4(acc[i][0], acc[i][1], acc[i][2], acc[i][3]);
        *(float4*)&O[((size_t)b * NS + q) * ND + h * NDH + tx * 4] = r4;
    }
}

// ---------------- loss -------------------------------------------------------
__global__ __launch_bounds__(512) void loss_row_k(const float* __restrict__ logits,
                                                  const int* __restrict__ idx,
                                                  const int* __restrict__ mask,
                                                  float* __restrict__ nll) {
    int row = blockIdx.x;
    int b = row / NS, s = row % NS;
    const float* lr = logits + (size_t)row * NV;
    int tid = threadIdx.x;
    __shared__ float red[512];
    float mx = -3.4e38f;
    for (int i = tid; i < NV; i += 512) mx = fmaxf(mx, lr[i]);
    red[tid] = mx; __syncthreads();
    for (int o = 256; o > 0; o >>= 1) { if (tid < o) red[tid] = fmaxf(red[tid], red[tid + o]); __syncthreads(); }
    mx = red[0]; __syncthreads();
    float sum = 0.f;
    for (int i = tid; i < NV; i += 512) sum += __expf(lr[i] - mx);
    red[tid] = sum; __syncthreads();
    for (int o = 256; o > 0; o >>= 1) { if (tid < o) red[tid] += red[tid + o]; __syncthreads(); }
    if (tid == 0) {
        int tgt = idx[b * (NS + 1) + s + 1];
        float lse = mx + logf(red[0]);
        nll[row] = (lse - lr[tgt]) * (float)mask[row];
    }
}

__global__ __launch_bounds__(1024) void loss_final_k(const float* __restrict__ nll,
                                                     float* __restrict__ out) {
    __shared__ float red[1024];
    int tid = threadIdx.x;
    red[tid] = nll[tid] + nll[tid + 1024];
    __syncthreads();
    for (int o = 512; o > 0; o >>= 1) { if (tid < o) red[tid] += red[tid + o]; __syncthreads(); }
    if (tid == 0) out[0] = red[0] * (1.0f / (float)NBS);
}

// ---------------- host orchestration -----------------------------------------
extern "C" void kernel_launch(void* const* d_in, const int* in_sizes, int n_in,
                              void* d_out, int out_size) {
    const int*   idx  = (const int*)d_in[0];
    const int*   mask = (const int*)d_in[1];
    const float* tok  = (const float*)d_in[2];
    const float* pos  = (const float*)d_in[3];
    const float* Wq   = (const float*)d_in[4];
    const float* bq   = (const float*)d_in[5];
    const float* Wk   = (const float*)d_in[6];
    const float* bk   = (const float*)d_in[7];
    const float* Wv   = (const float*)d_in[8];
    const float* bv   = (const float*)d_in[9];
    const float* Wo   = (const float*)d_in[10];
    const float* bo   = (const float*)d_in[11];
    const float* ln1g = (const float*)d_in[12];
    const float* ln1b = (const float*)d_in[13];
    const float* W1   = (const float*)d_in[14];
    const float* b1   = (const float*)d_in[15];
    const float* W2   = (const float*)d_in[16];
    const float* b2   = (const float*)d_in[17];
    const float* ln2g = (const float*)d_in[18];
    const float* ln2b = (const float*)d_in[19];
    const float* lnfg = (const float*)d_in[20];
    const float* lnfb = (const float*)d_in[21];
    const float* headw= (const float*)d_in[22];
    float* out = (float*)d_out;

    float *x, *h, *q, *k, *v, *o, *ff, *att, *nll;
    cudaGetSymbolAddress((void**)&x,   g_x);
    cudaGetSymbolAddress((void**)&h,   g_h);
    cudaGetSymbolAddress((void**)&q,   g_q);
    cudaGetSymbolAddress((void**)&k,   g_k);
    cudaGetSymbolAddress((void**)&v,   g_v);
    cudaGetSymbolAddress((void**)&o,   g_o);
    cudaGetSymbolAddress((void**)&ff,  g_ff);
    cudaGetSymbolAddress((void**)&att, g_att);
    cudaGetSymbolAddress((void**)&nll, g_nll);

    embed_k<<<NBS, 256>>>(idx, mask, tok, pos, x);

    dim3 gDD(ND / 64, NBS / 128);       // 8 x 16 = 128 CTAs (BN=64)
    dim3 gDF(NFF / 128, NBS / 128);     // 16 x 16 = 256 CTAs (BN=128)
    dim3 gqk(NS / 32, NS / 32, NB * NH);
    dim3 gav(NS / 32, NB * NH);

    for (int l = 0; l < NL; l++) {
        const float* wq = Wq + (size_t)l * ND * ND;
        const float* wk = Wk + (size_t)l * ND * ND;
        const float* wv = Wv + (size_t)l * ND * ND;
        const float* wo = Wo + (size_t)l * ND * ND;
        const float* w1 = W1 + (size_t)l * ND * NFF;
        const float* w2 = W2 + (size_t)l * NFF * ND;

        ln_k<<<NBS, 256>>>(x, ln1g + l * ND, ln1b + l * ND, h);
        gemm_tc<0, true, false, 64, true><<<gDD, 256>>>(h, wq, bq + l * ND, nullptr, q, NBS, ND, ND);
        gemm_tc<0, true, false, 64, true><<<gDD, 256>>>(h, wk, bk + l * ND, nullptr, k, NBS, ND, ND);
        gemm_tc<0, true, false, 64, true><<<gDD, 256>>>(h, wv, bv + l * ND, nullptr, v, NBS, ND, ND);
        qk_k<<<gqk, 256>>>(q, k, att);
        softmax_k<<<NB * NH * NS, 256>>>(att);
        av_k<<<gav, 256>>>(att, v, o);
        gemm_tc<0, true, true, 64, true><<<gDD, 256>>>(o, wo, bo + l * ND, x, x, NBS, ND, ND);
        ln_k<<<NBS, 256>>>(x, ln2g + l * ND, ln2b + l * ND, h);
        gemm_tc<1, true, false, 128, true><<<gDF, 256>>>(h, w1, b1 + l * NFF, nullptr, ff, NBS, NFF, ND);
        gemm_tc<0, true, true, 64, true><<<gDD, 256>>>(ff, w2, b2 + l * ND, x, x, NBS, ND, NFF);
    }

    ln_k<<<NBS, 256>>>(x, lnfg, lnfb, h);
    dim3 gHead((NV + 127) / 128, NBS / 128);
    gemm_tc<0, false, false, 128, false><<<gHead, 256>>>(h, headw, nullptr, nullptr, out, NBS, NV, ND);

    loss_row_k<<<NBS, 512>>>(out, idx, mask, nll);
    loss_final_k<<<1, 1024>>>(nll, out + (size_t)NBS * NV);
}